// round 13
// baseline (speedup 1.0000x reference)
#include <cuda_runtime.h>
#include <cuda_fp16.h>
#include <math.h>
#include <stdint.h>

#define Bn   16384
#define OBSn 376
#define Hn   512
#define Mn   8
#define L1n  3
#define Tn   50
#define An   17
#define LOGS2PI 0.9189385332046727f

// ===================== helpers =====================
__device__ __forceinline__ uint32_t smem_to_u32(const void* p) {
    uint32_t a;
    asm("{ .reg .u64 t; cvta.to.shared.u64 t, %1; cvt.u32.u64 %0, t; }" : "=r"(a) : "l"(p));
    return a;
}
#define LDSM4(r0, r1, r2, r3, addr) \
    asm volatile("ldmatrix.sync.aligned.m8n8.x4.shared.b16 {%0,%1,%2,%3}, [%4];" \
        : "=r"(r0), "=r"(r1), "=r"(r2), "=r"(r3) : "r"(addr))
#define MMA16816(d, a, b0v, b1v) \
    asm volatile("mma.sync.aligned.m16n8k16.row.col.f32.f16.f16.f32 " \
        "{%0,%1,%2,%3}, {%4,%5,%6,%7}, {%8,%9}, {%0,%1,%2,%3};" \
        : "+f"((d)[0]), "+f"((d)[1]), "+f"((d)[2]), "+f"((d)[3]) \
        : "r"((a)[0]), "r"((a)[1]), "r"((a)[2]), "r"((a)[3]), "r"(b0v), "r"(b1v))
#define CP_ASYNC16(dst, src) \
    asm volatile("cp.async.cg.shared.global [%0], [%1], 16;" :: "r"(dst), "l"(src) : "memory")
#define CP_COMMIT() asm volatile("cp.async.commit_group;" ::: "memory")
template<int N> __device__ __forceinline__ void cp_wait() {
    asm volatile("cp.async.wait_group %0;" :: "n"(N) : "memory");
}

__device__ __forceinline__ uint32_t packh2(float a, float b) {
    __half2 h = __floats2half2_rn(a, b);
    return *reinterpret_cast<uint32_t*>(&h);
}
__device__ __forceinline__ float2 h2f2(uint32_t u) {
    __half2 h = *reinterpret_cast<__half2*>(&u);
    return __half22float2(h);
}

// ===================== scratch =====================
__device__ float d_probsA[(size_t)Bn * L1n * 64];
__device__ float d_probsC[(size_t)Bn * L1n * 64];
__device__ float d_actorOut[(size_t)Bn * An];
__device__ float d_cst[32];
__device__ int   d_is64;

// activation planes (fp16)
__device__ __align__(16) __half p_x[(size_t)Bn * 384];
__device__ __align__(16) __half p_h1[(size_t)Bn * 512];
__device__ __align__(16) __half p_fs[(size_t)Bn * 512];
__device__ __align__(16) __half p_rel[(size_t)Bn * 512];
__device__ __align__(16) __half p_outc[(size_t)Bn * 4096];
__device__ __align__(16) __half p_outa[(size_t)Bn * 4096];
__device__ __align__(16) __half p_gc0[(size_t)Bn * 4096];
__device__ __align__(16) __half p_gc1[(size_t)Bn * 4096];
__device__ __align__(16) __half p_gc2[(size_t)Bn * 4096];
__device__ __align__(16) __half p_ga0[(size_t)Bn * 4096];
__device__ __align__(16) __half p_ga1[(size_t)Bn * 4096];

// transposed weights: [slab][N][Kpad] fp16
__device__ __align__(16) __half wt_e1[(size_t)512 * 384];
__device__ __align__(16) __half wt_e2[(size_t)512 * 512];
__device__ __align__(16) __half wt_ar[(size_t)3 * 64 * 512];
__device__ __align__(16) __half wt_cr[(size_t)3 * 64 * 512];
__device__ __align__(16) __half wt_a[(size_t)24 * 512 * 512];
__device__ __align__(16) __half wt_c[(size_t)24 * 512 * 512];
__device__ __align__(16) __half wt_af[(size_t)64 * 4096];

// ===================== fused prolog: splitx + detect + prep =====================
__global__ void prolog_kernel(const float* __restrict__ x, __half* __restrict__ xp,
                              const int* __restrict__ ti,
                              const float* __restrict__ abf, const float* __restrict__ cbf,
                              const float* __restrict__ logstd) {
    const int nb_split = (Bn * 96) / 256;
    if (blockIdx.x < nb_split) {
        const int gid = blockIdx.x * 256 + threadIdx.x;
        const int b = gid / 96, c4 = (gid % 96) * 4;
        float v[4];
#pragma unroll
        for (int e = 0; e < 4; ++e) {
            const int c = c4 + e;
            v[e] = (c < OBSn) ? x[(size_t)b * OBSn + c] : 0.f;
        }
        uint2 o;
        o.x = packh2(v[0], v[1]);
        o.y = packh2(v[2], v[3]);
        *(uint2*)(xp + (size_t)b * 384 + c4) = o;
    } else if (blockIdx.x == nb_split) {
        __shared__ int ok;
        if (threadIdx.x == 0) ok = 1;
        __syncthreads();
        for (int i = threadIdx.x; i < 1024; i += 256) {
            int v = ti[i];
            bool good = (i & 1) ? (v == 0) : (v >= 0 && v < Tn);
            if (!good) atomicAnd(&ok, 0);
        }
        __syncthreads();
        if (threadIdx.x == 0) d_is64 = ok;
    } else {
        const int t = threadIdx.x;
        if (t < An) {
            float s = 0.f;
            for (int m = 0; m < Mn; m++) s += abf[m * An + t];
            d_cst[t] = s;
        }
        if (t == 17) {
            float s = 0.f;
            for (int m = 0; m < Mn; m++) s += cbf[m];
            d_cst[19] = s;
        }
        if (t == 18) {
            float lp = 0.f, en = 0.f;
            for (int a = 0; a < An; a++) {
                lp += -logstd[a] - LOGS2PI;
                en += 0.5f + LOGS2PI + logstd[a];
            }
            d_cst[17] = lp;
            d_cst[18] = en;
        }
    }
}

// ===================== fused weight transpose (all 7 groups, one launch) =====================
__device__ __forceinline__ void tconv_body(const float* W, __half* Wt,
                                           int K, int Nsrc, int Kpad, int Nalloc,
                                           int bx, int by, int bz) {
    __shared__ float t[32][33];
    W  += (size_t)bz * K * Nsrc;
    Wt += (size_t)bz * Nalloc * Kpad;
    const int k0 = bx * 32, n0 = by * 32;
    const int tx = threadIdx.x & 31, ty = threadIdx.x >> 5;
    for (int i = ty; i < 32; i += 8) {
        int k = k0 + i, n = n0 + tx;
        t[i][tx] = (k < K && n < Nsrc) ? W[(size_t)k * Nsrc + n] : 0.f;
    }
    __syncthreads();
    for (int i = ty; i < 32; i += 8) {
        int n = n0 + i, k = k0 + tx;
        if (k < Kpad)
            Wt[(size_t)n * Kpad + k] = __float2half_rn(t[tx][i]);
    }
}

__global__ void tconv_all(const float* W1, const float* W2, const float* arW, const float* crW,
                          const float* aW, const float* cW, const float* aWf,
                          __half* we1, __half* we2, __half* war, __half* wcr,
                          __half* wa, __half* wc, __half* waf) {
    int bid = blockIdx.x;
    if (bid < 192) {
        tconv_body(W1, we1, OBSn, 512, 384, 512, bid % 12, bid / 12, 0);
    } else if (bid < 448) {
        bid -= 192;
        tconv_body(W2, we2, 512, 512, 512, 512, bid % 16, bid / 16, 0);
    } else if (bid < 544) {
        bid -= 448;
        int z = bid / 32, r = bid % 32;
        tconv_body(arW, war, 512, 64, 512, 64, r % 16, r / 16, z);
    } else if (bid < 640) {
        bid -= 544;
        int z = bid / 32, r = bid % 32;
        tconv_body(crW, wcr, 512, 64, 512, 64, r % 16, r / 16, z);
    } else if (bid < 6784) {
        bid -= 640;
        int z = bid / 256, r = bid % 256;
        tconv_body(aW, wa, 512, 512, 512, 512, r % 16, r / 16, z);
    } else if (bid < 12928) {
        bid -= 6784;
        int z = bid / 256, r = bid % 256;
        tconv_body(cW, wc, 512, 512, 512, 512, r % 16, r / 16, z);
    } else {
        bid -= 12928;
        tconv_body(aWf, waf, 4096, An, 4096, 64, bid % 128, bid / 128, 0);
    }
}

// ===================== generic fp16 GEMM (encoder/final) =====================
template<int NT, int WARPS_M, int ACT, int EPI>  // EPI: 0 fp32 C, 1 fp16 plane
__global__ __launch_bounds__(256, 2) void mmagemm(
    const __half* __restrict__ A, int lda, long long a_off,
    const __half* __restrict__ Wt, int Kpad, long long w_bs,
    const float* __restrict__ bias, int b_bs,
    float* __restrict__ C, __half* __restrict__ Ch, int ldc, long long c_off,
    int N_STORE, int NC)
{
    extern __shared__ char smem[];
    const uint32_t sb = smem_to_u32(smem);
    const int tid = threadIdx.x, wid = tid >> 5, lane = tid & 31;
    const int m0 = blockIdx.x * 128;
    const int n0g = blockIdx.y * NT;
    const int zb = blockIdx.z;
    A    += (size_t)zb * a_off;
    Wt   += (size_t)zb * w_bs + (size_t)n0g * Kpad;
    bias += (size_t)zb * b_bs + n0g;

    constexpr int MT = 128 / (16 * WARPS_M);
    constexpr int BB = NT * 128;
    constexpr int STAGE = 16384 + BB;
    const int wm0 = (wid % WARPS_M) * (MT * 16);
    const int wn0 = (wid / WARPS_M) * 32;

    float acc[MT][4][4];
#pragma unroll
    for (int mt = 0; mt < MT; ++mt)
#pragma unroll
        for (int nt = 0; nt < 4; ++nt)
#pragma unroll
            for (int e = 0; e < 4; ++e) acc[mt][nt][e] = 0.f;

    auto issue = [&](int c, int buf) {
        const int k0 = c << 6;
        const uint32_t dbase = sb + buf * STAGE;
#pragma unroll
        for (int it = 0; it < 4; ++it) {
            const int seg = it * 256 + tid;
            const int r = seg >> 3;
            const int ksb = (seg & 7) * 16;
            const int kelt = k0 + (seg & 7) * 8;
            const uint32_t doff = (uint32_t)r * 128 + ((uint32_t)ksb ^ (((uint32_t)r & 7) << 4));
            CP_ASYNC16(dbase + doff, A + (size_t)(m0 + r) * lda + kelt);
        }
#pragma unroll
        for (int it = 0; it < NT / 32; ++it) {
            const int seg = it * 256 + tid;
            const int r = seg >> 3;
            const int ksb = (seg & 7) * 16;
            const int kelt = k0 + (seg & 7) * 8;
            const uint32_t doff = (uint32_t)r * 128 + ((uint32_t)ksb ^ (((uint32_t)r & 7) << 4));
            CP_ASYNC16(dbase + 16384 + doff, Wt + (size_t)r * Kpad + kelt);
        }
        CP_COMMIT();
    };

    auto compute = [&](int buf) {
        const uint32_t ab = sb + buf * STAGE;
        const uint32_t bb = ab + 16384;
        const uint32_t xm = ((uint32_t)lane & 7) << 4;
        const int ra = ((lane >> 3) & 1) * 8 + (lane & 7);
        const int ka = ((lane >> 4) & 1) * 16;
        const int rb = ((lane >> 4) & 1) * 8 + (lane & 7);
        const int kb = ((lane >> 3) & 1) * 16;
#pragma unroll
        for (int s = 0; s < 4; ++s) {
            const int ksb = s * 32;
            uint32_t Ah[MT][4], Bh[4][2];
#pragma unroll
            for (int mt = 0; mt < MT; ++mt) {
                const uint32_t off = (uint32_t)(wm0 + mt * 16 + ra) * 128 +
                                     (((uint32_t)(ksb + ka)) ^ xm);
                LDSM4(Ah[mt][0], Ah[mt][1], Ah[mt][2], Ah[mt][3], ab + off);
            }
#pragma unroll
            for (int p = 0; p < 2; ++p) {
                const uint32_t off = (uint32_t)(wn0 + p * 16 + rb) * 128 +
                                     (((uint32_t)(ksb + kb)) ^ xm);
                LDSM4(Bh[2 * p][0], Bh[2 * p][1], Bh[2 * p + 1][0], Bh[2 * p + 1][1], bb + off);
            }
#pragma unroll
            for (int mt = 0; mt < MT; ++mt)
#pragma unroll
                for (int nt = 0; nt < 4; ++nt)
                    MMA16816(acc[mt][nt], Ah[mt], Bh[nt][0], Bh[nt][1]);
        }
    };

    issue(0, 0);
    issue(1, 1);
    for (int c = 0; c < NC; ++c) {
        cp_wait<1>();
        __syncthreads();
        if (c + 2 < NC) issue(c + 2, (c + 2) % 3);
        else CP_COMMIT();
        compute(c % 3);
    }

    const int g = lane >> 2, t = lane & 3;
#pragma unroll
    for (int mt = 0; mt < MT; ++mt) {
#pragma unroll
        for (int nt = 0; nt < 4; ++nt) {
            const int col = wn0 + nt * 8 + t * 2;
            float v0 = acc[mt][nt][0], v1 = acc[mt][nt][1];
            float v2 = acc[mt][nt][2], v3 = acc[mt][nt][3];
            const int row0 = m0 + wm0 + mt * 16 + g;
            if (EPI == 1) {
                const float bv0 = bias[col], bv1 = bias[col + 1];
                v0 += bv0; v1 += bv1; v2 += bv0; v3 += bv1;
                if (ACT == 1) { v0 = fmaxf(v0, 0.f); v1 = fmaxf(v1, 0.f); v2 = fmaxf(v2, 0.f); v3 = fmaxf(v3, 0.f); }
                if (ACT == 2) { v0 = tanhf(v0); v1 = tanhf(v1); v2 = tanhf(v2); v3 = tanhf(v3); }
                const size_t o0 = (size_t)zb * c_off + (size_t)row0 * ldc + n0g + col;
                const size_t o1 = (size_t)zb * c_off + (size_t)(row0 + 8) * ldc + n0g + col;
                *(uint32_t*)(Ch + o0) = packh2(v0, v1);
                *(uint32_t*)(Ch + o1) = packh2(v2, v3);
            } else {
                const int rem = N_STORE - n0g;
                const float bv0 = (col < rem) ? bias[col] : 0.f;
                const float bv1 = (col + 1 < rem) ? bias[col + 1] : 0.f;
                v0 += bv0; v1 += bv1; v2 += bv0; v3 += bv1;
                if (ACT == 1) { v0 = fmaxf(v0, 0.f); v1 = fmaxf(v1, 0.f); v2 = fmaxf(v2, 0.f); v3 = fmaxf(v3, 0.f); }
                if (ACT == 2) { v0 = tanhf(v0); v1 = tanhf(v1); v2 = tanhf(v2); v3 = tanhf(v3); }
                float* Cb = C + (size_t)zb * c_off + n0g;
                if (col < rem) {
                    Cb[(size_t)row0 * ldc + col] = v0;
                    Cb[(size_t)(row0 + 8) * ldc + col] = v2;
                }
                if (col + 1 < rem) {
                    Cb[(size_t)row0 * ldc + col + 1] = v1;
                    Cb[(size_t)(row0 + 8) * ldc + col + 1] = v3;
                }
            }
        }
    }
}

// ===================== routing GEMM, both nets one launch (z=6) =====================
__global__ __launch_bounds__(256, 2) void routegemm(
    const __half* __restrict__ A,
    const __half* __restrict__ WtA, const __half* __restrict__ WtC,
    const float* __restrict__ rbA, const float* __restrict__ rbC,
    float* __restrict__ pA, float* __restrict__ pC)
{
    extern __shared__ char smem[];
    const uint32_t sb = smem_to_u32(smem);
    const int tid = threadIdx.x, wid = tid >> 5, lane = tid & 31;
    const int m0 = blockIdx.x * 128;
    const int zb = blockIdx.z;
    const int net = zb / 3, l = zb % 3;
    const __half* Wt = (net ? WtC : WtA) + (size_t)l * 64 * 512;
    const float* bias = (net ? rbC : rbA) + l * 64;
    float* C = (net ? pC : pA) + (size_t)l * 64;

    constexpr int STAGE = 16384 + 8192;
    const int wm0 = (wid % 4) * 32;
    const int wn0 = (wid / 4) * 32;

    float acc[2][4][4];
#pragma unroll
    for (int mt = 0; mt < 2; ++mt)
#pragma unroll
        for (int nt = 0; nt < 4; ++nt)
#pragma unroll
            for (int e = 0; e < 4; ++e) acc[mt][nt][e] = 0.f;

    auto issue = [&](int c, int buf) {
        const int k0 = c << 6;
        const uint32_t dbase = sb + buf * STAGE;
#pragma unroll
        for (int it = 0; it < 4; ++it) {
            const int seg = it * 256 + tid;
            const int r = seg >> 3;
            const int ks = (seg & 7) * 16;
            const uint32_t doff = (uint32_t)r * 128 + ((uint32_t)ks ^ (((uint32_t)r & 7) << 4));
            CP_ASYNC16(dbase + doff, A + (size_t)(m0 + r) * Hn + k0 + (seg & 7) * 8);
        }
        {
#pragma unroll
            for (int it = 0; it < 2; ++it) {
                const int s2 = it * 256 + tid;
                const int r = s2 >> 3;
                const int ks = (s2 & 7) * 16;
                const uint32_t doff = (uint32_t)r * 128 + ((uint32_t)ks ^ (((uint32_t)r & 7) << 4));
                CP_ASYNC16(dbase + 16384 + doff, Wt + (size_t)r * 512 + k0 + (s2 & 7) * 8);
            }
        }
        CP_COMMIT();
    };

    auto compute = [&](int buf) {
        const uint32_t ab = sb + buf * STAGE;
        const uint32_t bb = ab + 16384;
        const uint32_t xm = ((uint32_t)lane & 7) << 4;
        const int ra = ((lane >> 3) & 1) * 8 + (lane & 7);
        const int ka = ((lane >> 4) & 1) * 16;
        const int rb = ((lane >> 4) & 1) * 8 + (lane & 7);
        const int kb = ((lane >> 3) & 1) * 16;
#pragma unroll
        for (int s = 0; s < 4; ++s) {
            const int ksb = s * 32;
            uint32_t Ah[2][4], Bh[4][2];
#pragma unroll
            for (int mt = 0; mt < 2; ++mt) {
                const uint32_t off = (uint32_t)(wm0 + mt * 16 + ra) * 128 +
                                     (((uint32_t)(ksb + ka)) ^ xm);
                LDSM4(Ah[mt][0], Ah[mt][1], Ah[mt][2], Ah[mt][3], ab + off);
            }
#pragma unroll
            for (int p = 0; p < 2; ++p) {
                const uint32_t off = (uint32_t)(wn0 + p * 16 + rb) * 128 +
                                     (((uint32_t)(ksb + kb)) ^ xm);
                LDSM4(Bh[2 * p][0], Bh[2 * p][1], Bh[2 * p + 1][0], Bh[2 * p + 1][1], bb + off);
            }
#pragma unroll
            for (int mt = 0; mt < 2; ++mt)
#pragma unroll
                for (int nt = 0; nt < 4; ++nt)
                    MMA16816(acc[mt][nt], Ah[mt], Bh[nt][0], Bh[nt][1]);
        }
    };

    issue(0, 0);
    issue(1, 1);
    for (int c = 0; c < 8; ++c) {
        cp_wait<1>();
        __syncthreads();
        if (c + 2 < 8) issue(c + 2, (c + 2) % 3);
        else CP_COMMIT();
        compute(c % 3);
    }

    const int g = lane >> 2, t = lane & 3;
#pragma unroll
    for (int mt = 0; mt < 2; ++mt) {
#pragma unroll
        for (int nt = 0; nt < 4; ++nt) {
            const int col = wn0 + nt * 8 + t * 2;
            if (col < 64) {
                const float bv0 = bias[col], bv1 = bias[col + 1];
                const int row0 = m0 + wm0 + mt * 16 + g;
                C[(size_t)row0 * (L1n * 64) + col]     = acc[mt][nt][0] + bv0;
                C[(size_t)row0 * (L1n * 64) + col + 1] = acc[mt][nt][1] + bv1;
                C[(size_t)(row0 + 8) * (L1n * 64) + col]     = acc[mt][nt][2] + bv0;
                C[(size_t)(row0 + 8) * (L1n * 64) + col + 1] = acc[mt][nt][3] + bv1;
            }
        }
    }
}

// ===================== module GEMM: 128x128, 256 thr, z=16 =====================
__global__ __launch_bounds__(256, 2) void modgemm2(
    const __half* __restrict__ Ac, const __half* __restrict__ Aa, int lda, int amod,
    const __half* __restrict__ Wc, const __half* __restrict__ Wa,
    const float* __restrict__ biasC, const float* __restrict__ biasA,
    __half* __restrict__ outC, __half* __restrict__ outA)
{
    extern __shared__ char smem[];
    const uint32_t sb = smem_to_u32(smem);
    const int tid = threadIdx.x, wid = tid >> 5, lane = tid & 31;
    const int m0 = blockIdx.x * 128;
    const int n0g = blockIdx.y * 128;
    const int zb = blockIdx.z;
    const int net = zb >> 3, m = zb & 7;
    const __half* A  = (net ? Aa : Ac) + (size_t)m * amod;
    const __half* Wt = (net ? Wa : Wc) + (size_t)m * 512 * 512 + (size_t)n0g * 512;
    const float* bias = (net ? biasA : biasC) + m * 512 + n0g;
    __half* Ch = net ? outA : outC;

    constexpr int STAGE = 32768;
    const int wm0 = (wid & 1) * 64;
    const int wn0 = (wid >> 1) * 32;

    float acc[4][4][4];
#pragma unroll
    for (int mt = 0; mt < 4; ++mt)
#pragma unroll
        for (int nt = 0; nt < 4; ++nt)
#pragma unroll
            for (int e = 0; e < 4; ++e) acc[mt][nt][e] = 0.f;

    auto issue = [&](int c, int buf) {
        const int k0 = c << 6;
        const uint32_t dbase = sb + buf * STAGE;
#pragma unroll
        for (int it = 0; it < 4; ++it) {
            const int seg = it * 256 + tid;
            const int r = seg >> 3;
            const int ks = (seg & 7) * 16;
            const uint32_t doff = (uint32_t)r * 128 + ((uint32_t)ks ^ (((uint32_t)r & 7) << 4));
            CP_ASYNC16(dbase + doff, A + (size_t)(m0 + r) * lda + k0 + (seg & 7) * 8);
        }
#pragma unroll
        for (int it = 0; it < 4; ++it) {
            const int seg = it * 256 + tid;
            const int r = seg >> 3;
            const int ks = (seg & 7) * 16;
            const uint32_t doff = (uint32_t)r * 128 + ((uint32_t)ks ^ (((uint32_t)r & 7) << 4));
            CP_ASYNC16(dbase + 16384 + doff, Wt + (size_t)r * 512 + k0 + (seg & 7) * 8);
        }
        CP_COMMIT();
    };

    auto compute = [&](int buf) {
        const uint32_t ab = sb + buf * STAGE;
        const uint32_t bb = ab + 16384;
        const uint32_t xm = ((uint32_t)lane & 7) << 4;
        const int ra = ((lane >> 3) & 1) * 8 + (lane & 7);
        const int ka = ((lane >> 4) & 1) * 16;
        const int rb = ((lane >> 4) & 1) * 8 + (lane & 7);
        const int kb = ((lane >> 3) & 1) * 16;
#pragma unroll
        for (int s = 0; s < 4; ++s) {
            const int ksb = s * 32;
            uint32_t Ah[4][4], Bh[4][2];
#pragma unroll
            for (int mt = 0; mt < 4; ++mt) {
                const uint32_t off = (uint32_t)(wm0 + mt * 16 + ra) * 128 +
                                     (((uint32_t)(ksb + ka)) ^ xm);
                LDSM4(Ah[mt][0], Ah[mt][1], Ah[mt][2], Ah[mt][3], ab + off);
            }
#pragma unroll
            for (int p = 0; p < 2; ++p) {
                const uint32_t off = (uint32_t)(wn0 + p * 16 + rb) * 128 +
                                     (((uint32_t)(ksb + kb)) ^ xm);
                LDSM4(Bh[2 * p][0], Bh[2 * p][1], Bh[2 * p + 1][0], Bh[2 * p + 1][1], bb + off);
            }
#pragma unroll
            for (int mt = 0; mt < 4; ++mt)
#pragma unroll
                for (int nt = 0; nt < 4; ++nt)
                    MMA16816(acc[mt][nt], Ah[mt], Bh[nt][0], Bh[nt][1]);
        }
    };

    issue(0, 0);
    issue(1, 1);
    for (int c = 0; c < 8; ++c) {
        cp_wait<1>();
        __syncthreads();
        if (c + 2 < 8) issue(c + 2, (c + 2) % 3);
        else CP_COMMIT();
        compute(c % 3);
    }

    const int g = lane >> 2, t = lane & 3;
#pragma unroll
    for (int mt = 0; mt < 4; ++mt) {
#pragma unroll
        for (int nt = 0; nt < 4; ++nt) {
            const int col = wn0 + nt * 8 + t * 2;
            const float bv0 = bias[col], bv1 = bias[col + 1];
            float v0 = fmaxf(acc[mt][nt][0] + bv0, 0.f);
            float v1 = fmaxf(acc[mt][nt][1] + bv1, 0.f);
            float v2 = fmaxf(acc[mt][nt][2] + bv0, 0.f);
            float v3 = fmaxf(acc[mt][nt][3] + bv1, 0.f);
            const int row0 = m0 + wm0 + mt * 16 + g;
            const size_t o0 = (size_t)row0 * 4096 + m * 512 + n0g + col;
            const size_t o1 = (size_t)(row0 + 8) * 4096 + m * 512 + n0g + col;
            *(uint32_t*)(Ch + o0) = packh2(v0, v1);
            *(uint32_t*)(Ch + o1) = packh2(v2, v3);
        }
    }
}

// ===================== rel = relu(fs * emb[idx]) -> fp16 plane =====================
__global__ void rel_kernel(const __half* __restrict__ fsp, const void* __restrict__ tidx,
                           const float* __restrict__ emb, __half* __restrict__ rp) {
    const int gid = blockIdx.x * blockDim.x + threadIdx.x;
    const int b = gid >> 7, h4 = (gid & 127) * 4;
    long long ti;
    if (d_is64) ti = ((const long long*)tidx)[b];
    else        ti = (long long)((const int*)tidx)[b];
    const size_t base = (size_t)b * Hn + h4;
    uint2 fu = *(const uint2*)(fsp + base);
    float2 f0 = h2f2(fu.x), f1 = h2f2(fu.y);
    float4 e = *(const float4*)(emb + (size_t)ti * Hn + h4);
    float r0 = fmaxf(f0.x * e.x, 0.f);
    float r1 = fmaxf(f0.y * e.y, 0.f);
    float r2 = fmaxf(f1.x * e.z, 0.f);
    float r3 = fmaxf(f1.y * e.w, 0.f);
    uint2 o;
    o.x = packh2(r0, r1);
    o.y = packh2(r2, r3);
    *(uint2*)(rp + base) = o;
}

// ===================== softmax over groups of 8 =====================
__global__ void softmax_kernel(float* __restrict__ pA, float* __restrict__ pC) {
    const int gid = blockIdx.x * blockDim.x + threadIdx.x;
    const int per = Bn * L1n * 8;
    float* p = (gid < per) ? (pA + (size_t)gid * 8) : (pC + (size_t)(gid - per) * 8);
    float v[8], mx = -1e30f;
#pragma unroll
    for (int j = 0; j < 8; j++) { v[j] = p[j]; mx = fmaxf(mx, v[j]); }
    float s = 0.f;
#pragma unroll
    for (int j = 0; j < 8; j++) { v[j] = __expf(v[j] - mx); s += v[j]; }
    const float inv = 1.f / s;
#pragma unroll
    for (int j = 0; j < 8; j++) p[j] = v[j] * inv;
}

// ===================== fused mix, 4 samples per 512-thread block =====================
__global__ __launch_bounds__(512) void mix2_kernel(
    const float* __restrict__ pC, const float* __restrict__ pA,
    const __half* __restrict__ opc, const __half* __restrict__ opa,
    __half* __restrict__ gc, __half* __restrict__ ga) {
    __shared__ float p[4][64];
    const int net = blockIdx.y, tid = threadIdx.x;
    const int sub = tid >> 7, t = tid & 127;
    const int b = blockIdx.x * 4 + sub;
    const float* probs = net ? pA : pC;
    const __half* op = net ? opa : opc;
    __half* gp = net ? ga : gc;
    if (t < 64) p[sub][t] = probs[(size_t)b * (L1n * 64) + t];
    __syncthreads();
    const size_t base = (size_t)b * 4096 + t * 4;
    float o[8][4];
#pragma unroll
    for (int j = 0; j < 8; j++) {
        uint2 u = *(const uint2*)(op + base + j * 512);
        float2 a = h2f2(u.x), c = h2f2(u.y);
        o[j][0] = a.x; o[j][1] = a.y; o[j][2] = c.x; o[j][3] = c.y;
    }
#pragma unroll
    for (int i = 0; i < 8; i++) {
        float a0 = 0.f, a1 = 0.f, a2 = 0.f, a3 = 0.f;
#pragma unroll
        for (int j = 0; j < 8; j++) {
            const float w = p[sub][i * 8 + j];
            a0 = fmaf(w, o[j][0], a0);
            a1 = fmaf(w, o[j][1], a1);
            a2 = fmaf(w, o[j][2], a2);
            a3 = fmaf(w, o[j][3], a3);
        }
        uint2 u;
        u.x = packh2(a0, a1);
        u.y = packh2(a2, a3);
        *(uint2*)(gp + base + i * 512) = u;
    }
}

// ===================== critic + pack fused =====================
__global__ void critpack_kernel(const __half* __restrict__ gp, const float* __restrict__ wf,
                                const float* __restrict__ actorOut, float* __restrict__ out) {
    const int w = (blockIdx.x * blockDim.x + threadIdx.x) >> 5;
    const int lane = threadIdx.x & 31;
    const size_t off = (size_t)w * (Mn * Hn);
    float s = 0.f;
    for (int i = lane * 2; i < Mn * Hn; i += 64) {
        float2 g = h2f2(*(const uint32_t*)(gp + off + i));
        float2 f = *(const float2*)(wf + i);
        s = fmaf(g.x, f.x, s);
        s = fmaf(g.y, f.y, s);
    }
#pragma unroll
    for (int o = 16; o > 0; o >>= 1) s += __shfl_xor_sync(0xFFFFFFFFu, s, o);
    if (lane < An)       out[(size_t)w * 20 + lane] = actorOut[(size_t)w * An + lane];
    else if (lane == 17) out[(size_t)w * 20 + 17] = d_cst[17];
    else if (lane == 18) out[(size_t)w * 20 + 18] = d_cst[18];
    else if (lane == 19) out[(size_t)w * 20 + 19] = s + d_cst[19];
}

// ===================== host =====================
extern "C" void kernel_launch(void* const* d_in, const int* in_sizes, int n_in,
                              void* d_out, int out_size) {
    const float* x      = (const float*)d_in[0];
    const void*  tidx   = d_in[1];
    const float* W1     = (const float*)d_in[2];
    const float* b1     = (const float*)d_in[3];
    const float* W2     = (const float*)d_in[4];
    const float* b2     = (const float*)d_in[5];
    const float* emb    = (const float*)d_in[6];
    const float* a_rW   = (const float*)d_in[7];
    const float* a_rb   = (const float*)d_in[8];
    const float* c_rW   = (const float*)d_in[9];
    const float* c_rb   = (const float*)d_in[10];
    const float* a_W    = (const float*)d_in[11];
    const float* a_b    = (const float*)d_in[12];
    const float* a_Wf   = (const float*)d_in[13];
    const float* a_bf   = (const float*)d_in[14];
    const float* c_W    = (const float*)d_in[15];
    const float* c_b    = (const float*)d_in[16];
    const float* c_Wf   = (const float*)d_in[17];
    const float* c_bf   = (const float*)d_in[18];
    const float* logstd = (const float*)d_in[19];
    float* out = (float*)d_out;

    float *pA, *pC, *actorOut, *cst;
    __half *xp, *h1p, *fsp, *rp, *opc, *opa, *gc0, *gc1, *gc2, *ga0, *ga1;
    __half *we1, *we2, *war, *wcr, *wa, *wc, *waf;
    cudaGetSymbolAddress((void**)&pA, d_probsA);
    cudaGetSymbolAddress((void**)&pC, d_probsC);
    cudaGetSymbolAddress((void**)&actorOut, d_actorOut);
    cudaGetSymbolAddress((void**)&cst, d_cst);
    cudaGetSymbolAddress((void**)&xp, p_x);
    cudaGetSymbolAddress((void**)&h1p, p_h1);
    cudaGetSymbolAddress((void**)&fsp, p_fs);
    cudaGetSymbolAddress((void**)&rp, p_rel);
    cudaGetSymbolAddress((void**)&opc, p_outc);
    cudaGetSymbolAddress((void**)&opa, p_outa);
    cudaGetSymbolAddress((void**)&gc0, p_gc0);
    cudaGetSymbolAddress((void**)&gc1, p_gc1);
    cudaGetSymbolAddress((void**)&gc2, p_gc2);
    cudaGetSymbolAddress((void**)&ga0, p_ga0);
    cudaGetSymbolAddress((void**)&ga1, p_ga1);
    cudaGetSymbolAddress((void**)&we1, wt_e1);
    cudaGetSymbolAddress((void**)&we2, wt_e2);
    cudaGetSymbolAddress((void**)&war, wt_ar);
    cudaGetSymbolAddress((void**)&wcr, wt_cr);
    cudaGetSymbolAddress((void**)&wa, wt_a);
    cudaGetSymbolAddress((void**)&wc, wt_c);
    cudaGetSymbolAddress((void**)&waf, wt_af);

    const int SM128 = 3 * (16384 + 128 * 128);   // 98304
    const int SM64  = 3 * (16384 + 64 * 128);    // 73728
    const int SMRT  = 3 * (16384 + 8192);        // 73728
    cudaFuncSetAttribute(mmagemm<128, 2, 2, 1>, cudaFuncAttributeMaxDynamicSharedMemorySize, SM128);
    cudaFuncSetAttribute(mmagemm<64, 4, 0, 0>,  cudaFuncAttributeMaxDynamicSharedMemorySize, SM64);
    cudaFuncSetAttribute(routegemm, cudaFuncAttributeMaxDynamicSharedMemorySize, SMRT);
    cudaFuncSetAttribute(modgemm2, cudaFuncAttributeMaxDynamicSharedMemorySize, SM128);

    // prolog: splitx + detect + prep
    prolog_kernel<<<(Bn * 96) / 256 + 2, 256>>>(x, xp, (const int*)tidx, a_bf, c_bf, logstd);

    // all weight conversions in one launch
    tconv_all<<<13184, 256>>>(W1, W2, a_rW, c_rW, a_W, c_W, a_Wf,
                              we1, we2, war, wcr, wa, wc, waf);

    // encoder
    mmagemm<128, 2, 2, 1><<<dim3(128, 4, 1), 256, SM128>>>(
        xp, 384, 0, we1, 384, 0, b1, 0,
        nullptr, h1p, Hn, 0, Hn, 6);
    mmagemm<128, 2, 2, 1><<<dim3(128, 4, 1), 256, SM128>>>(
        h1p, Hn, 0, we2, 512, 0, b2, 0,
        nullptr, fsp, Hn, 0, Hn, 8);
    rel_kernel<<<(Bn * 128) / 256, 256>>>(fsp, tidx, emb, rp);

    // routing, both nets in one launch
    routegemm<<<dim3(128, 1, 6), 256, SMRT>>>(rp, war, wcr, a_rb, c_rb, pA, pC);
    softmax_kernel<<<(2 * Bn * L1n * 8) / 256, 256>>>(pA, pC);

    // fused module layers
    {
        const __half* gcp = fsp;
        const __half* gap = fsp;
        __half* gcd[3] = {gc0, gc1, gc2};
        __half* gad[3] = {ga0, ga1, ga0};
        for (int l = 0; l < L1n; l++) {
            modgemm2<<<dim3(Bn / 128, 4, 16), 256, SM128>>>(
                gcp, gap,
                (l == 0) ? Hn : (Mn * Hn), (l == 0) ? 0 : Hn,
                wc + (size_t)l * Mn * 512 * 512, wa + (size_t)l * Mn * 512 * 512,
                c_b + (size_t)l * Mn * Hn, a_b + (size_t)l * Mn * Hn,
                opc, opa);
            mix2_kernel<<<dim3(Bn / 4, 2), 512>>>(pC + (size_t)l * 64, pA + (size_t)l * 64,
                                                  opc, opa, gcd[l], gad[l]);
            gcp = gcd[l]; gap = gad[l];
        }
    }

    // actor final
    mmagemm<64, 4, 0, 0><<<dim3(128, 1, 1), 256, SM64>>>(
        ga0, Mn * Hn, 0, waf, 4096, 0, cst, 0,
        actorOut, nullptr, An, 0, An, 64);
    // critic dot + output pack fused
    critpack_kernel<<<Bn / 8, 256>>>(gc2, c_Wf, actorOut, out);
}

// round 14
// speedup vs baseline: 1.0491x; 1.0491x over previous
#include <cuda_runtime.h>
#include <cuda_fp16.h>
#include <math.h>
#include <stdint.h>

#define Bn   16384
#define OBSn 376
#define Hn   512
#define Mn   8
#define L1n  3
#define Tn   50
#define An   17
#define LOGS2PI 0.9189385332046727f

// ===================== helpers =====================
__device__ __forceinline__ uint32_t smem_to_u32(const void* p) {
    uint32_t a;
    asm("{ .reg .u64 t; cvta.to.shared.u64 t, %1; cvt.u32.u64 %0, t; }" : "=r"(a) : "l"(p));
    return a;
}
#define LDSM4(r0, r1, r2, r3, addr) \
    asm volatile("ldmatrix.sync.aligned.m8n8.x4.shared.b16 {%0,%1,%2,%3}, [%4];" \
        : "=r"(r0), "=r"(r1), "=r"(r2), "=r"(r3) : "r"(addr))
#define MMA16816(d, a, b0v, b1v) \
    asm volatile("mma.sync.aligned.m16n8k16.row.col.f32.f16.f16.f32 " \
        "{%0,%1,%2,%3}, {%4,%5,%6,%7}, {%8,%9}, {%0,%1,%2,%3};" \
        : "+f"((d)[0]), "+f"((d)[1]), "+f"((d)[2]), "+f"((d)[3]) \
        : "r"((a)[0]), "r"((a)[1]), "r"((a)[2]), "r"((a)[3]), "r"(b0v), "r"(b1v))
#define CP_ASYNC16(dst, src) \
    asm volatile("cp.async.cg.shared.global [%0], [%1], 16;" :: "r"(dst), "l"(src) : "memory")
#define CP_COMMIT() asm volatile("cp.async.commit_group;" ::: "memory")
template<int N> __device__ __forceinline__ void cp_wait() {
    asm volatile("cp.async.wait_group %0;" :: "n"(N) : "memory");
}

__device__ __forceinline__ uint32_t packh2(float a, float b) {
    __half2 h = __floats2half2_rn(a, b);
    return *reinterpret_cast<uint32_t*>(&h);
}
__device__ __forceinline__ float2 h2f2(uint32_t u) {
    __half2 h = *reinterpret_cast<__half2*>(&u);
    return __half22float2(h);
}

// ===================== scratch =====================
__device__ float d_probsA[(size_t)Bn * L1n * 64];
__device__ float d_probsC[(size_t)Bn * L1n * 64];
__device__ float d_actorOut[(size_t)Bn * An];
__device__ float d_cst[32];
__device__ int   d_is64;

// activation planes (fp16)
__device__ __align__(16) __half p_x[(size_t)Bn * 384];
__device__ __align__(16) __half p_h1[(size_t)Bn * 512];
__device__ __align__(16) __half p_fs[(size_t)Bn * 512];
__device__ __align__(16) __half p_rel[(size_t)Bn * 512];
__device__ __align__(16) __half p_outc[(size_t)Bn * 4096];
__device__ __align__(16) __half p_outa[(size_t)Bn * 4096];
__device__ __align__(16) __half p_gc0[(size_t)Bn * 4096];
__device__ __align__(16) __half p_gc1[(size_t)Bn * 4096];
__device__ __align__(16) __half p_gc2[(size_t)Bn * 4096];
__device__ __align__(16) __half p_ga0[(size_t)Bn * 4096];
__device__ __align__(16) __half p_ga1[(size_t)Bn * 4096];

// transposed weights: [slab][N][Kpad] fp16
__device__ __align__(16) __half wt_e1[(size_t)512 * 384];
__device__ __align__(16) __half wt_e2[(size_t)512 * 512];
__device__ __align__(16) __half wt_ar[(size_t)3 * 64 * 512];
__device__ __align__(16) __half wt_cr[(size_t)3 * 64 * 512];
__device__ __align__(16) __half wt_a[(size_t)24 * 512 * 512];
__device__ __align__(16) __half wt_c[(size_t)24 * 512 * 512];
__device__ __align__(16) __half wt_af[(size_t)64 * 4096];

// ===================== fused prolog: splitx + detect + prep =====================
__global__ void prolog_kernel(const float* __restrict__ x, __half* __restrict__ xp,
                              const int* __restrict__ ti,
                              const float* __restrict__ abf, const float* __restrict__ cbf,
                              const float* __restrict__ logstd) {
    const int nb_split = (Bn * 96) / 256;
    if (blockIdx.x < nb_split) {
        const int gid = blockIdx.x * 256 + threadIdx.x;
        const int b = gid / 96, c4 = (gid % 96) * 4;
        float v[4];
#pragma unroll
        for (int e = 0; e < 4; ++e) {
            const int c = c4 + e;
            v[e] = (c < OBSn) ? x[(size_t)b * OBSn + c] : 0.f;
        }
        uint2 o;
        o.x = packh2(v[0], v[1]);
        o.y = packh2(v[2], v[3]);
        *(uint2*)(xp + (size_t)b * 384 + c4) = o;
    } else if (blockIdx.x == nb_split) {
        __shared__ int ok;
        if (threadIdx.x == 0) ok = 1;
        __syncthreads();
        for (int i = threadIdx.x; i < 1024; i += 256) {
            int v = ti[i];
            bool good = (i & 1) ? (v == 0) : (v >= 0 && v < Tn);
            if (!good) atomicAnd(&ok, 0);
        }
        __syncthreads();
        if (threadIdx.x == 0) d_is64 = ok;
    } else {
        const int t = threadIdx.x;
        if (t < An) {
            float s = 0.f;
            for (int m = 0; m < Mn; m++) s += abf[m * An + t];
            d_cst[t] = s;
        }
        if (t == 17) {
            float s = 0.f;
            for (int m = 0; m < Mn; m++) s += cbf[m];
            d_cst[19] = s;
        }
        if (t == 18) {
            float lp = 0.f, en = 0.f;
            for (int a = 0; a < An; a++) {
                lp += -logstd[a] - LOGS2PI;
                en += 0.5f + LOGS2PI + logstd[a];
            }
            d_cst[17] = lp;
            d_cst[18] = en;
        }
    }
}

// ===================== fused weight transpose (all 7 groups, one launch) =====================
__device__ __forceinline__ void tconv_body(const float* W, __half* Wt,
                                           int K, int Nsrc, int Kpad, int Nalloc,
                                           int bx, int by, int bz) {
    __shared__ float t[32][33];
    W  += (size_t)bz * K * Nsrc;
    Wt += (size_t)bz * Nalloc * Kpad;
    const int k0 = bx * 32, n0 = by * 32;
    const int tx = threadIdx.x & 31, ty = threadIdx.x >> 5;
    for (int i = ty; i < 32; i += 8) {
        int k = k0 + i, n = n0 + tx;
        t[i][tx] = (k < K && n < Nsrc) ? W[(size_t)k * Nsrc + n] : 0.f;
    }
    __syncthreads();
    for (int i = ty; i < 32; i += 8) {
        int n = n0 + i, k = k0 + tx;
        if (k < Kpad)
            Wt[(size_t)n * Kpad + k] = __float2half_rn(t[tx][i]);
    }
}

__global__ void tconv_all(const float* W1, const float* W2, const float* arW, const float* crW,
                          const float* aW, const float* cW, const float* aWf,
                          __half* we1, __half* we2, __half* war, __half* wcr,
                          __half* wa, __half* wc, __half* waf) {
    int bid = blockIdx.x;
    if (bid < 192) {
        tconv_body(W1, we1, OBSn, 512, 384, 512, bid % 12, bid / 12, 0);
    } else if (bid < 448) {
        bid -= 192;
        tconv_body(W2, we2, 512, 512, 512, 512, bid % 16, bid / 16, 0);
    } else if (bid < 544) {
        bid -= 448;
        int z = bid / 32, r = bid % 32;
        tconv_body(arW, war, 512, 64, 512, 64, r % 16, r / 16, z);
    } else if (bid < 640) {
        bid -= 544;
        int z = bid / 32, r = bid % 32;
        tconv_body(crW, wcr, 512, 64, 512, 64, r % 16, r / 16, z);
    } else if (bid < 6784) {
        bid -= 640;
        int z = bid / 256, r = bid % 256;
        tconv_body(aW, wa, 512, 512, 512, 512, r % 16, r / 16, z);
    } else if (bid < 12928) {
        bid -= 6784;
        int z = bid / 256, r = bid % 256;
        tconv_body(cW, wc, 512, 512, 512, 512, r % 16, r / 16, z);
    } else {
        bid -= 12928;
        tconv_body(aWf, waf, 4096, An, 4096, 64, bid % 128, bid / 128, 0);
    }
}

// ===================== generic fp16 GEMM =====================
// EPI: 0 fp32 C, 1 fp16 plane, 2 fp16 plane + fused rel = relu(v * emb[tidx[row]][col])
template<int NT, int WARPS_M, int ACT, int EPI>
__global__ __launch_bounds__(256, 2) void mmagemm(
    const __half* __restrict__ A, int lda, long long a_off,
    const __half* __restrict__ Wt, int Kpad, long long w_bs,
    const float* __restrict__ bias, int b_bs,
    float* __restrict__ C, __half* __restrict__ Ch, int ldc, long long c_off,
    int N_STORE, int NC,
    const void* __restrict__ tidx, const float* __restrict__ emb,
    __half* __restrict__ relp)
{
    extern __shared__ char smem[];
    const uint32_t sb = smem_to_u32(smem);
    const int tid = threadIdx.x, wid = tid >> 5, lane = tid & 31;
    const int m0 = blockIdx.x * 128;
    const int n0g = blockIdx.y * NT;
    const int zb = blockIdx.z;
    A    += (size_t)zb * a_off;
    Wt   += (size_t)zb * w_bs + (size_t)n0g * Kpad;
    bias += (size_t)zb * b_bs + n0g;

    constexpr int MT = 128 / (16 * WARPS_M);
    constexpr int BB = NT * 128;
    constexpr int STAGE = 16384 + BB;
    const int wm0 = (wid % WARPS_M) * (MT * 16);
    const int wn0 = (wid / WARPS_M) * 32;

    float acc[MT][4][4];
#pragma unroll
    for (int mt = 0; mt < MT; ++mt)
#pragma unroll
        for (int nt = 0; nt < 4; ++nt)
#pragma unroll
            for (int e = 0; e < 4; ++e) acc[mt][nt][e] = 0.f;

    auto issue = [&](int c, int buf) {
        const int k0 = c << 6;
        const uint32_t dbase = sb + buf * STAGE;
#pragma unroll
        for (int it = 0; it < 4; ++it) {
            const int seg = it * 256 + tid;
            const int r = seg >> 3;
            const int ksb = (seg & 7) * 16;
            const int kelt = k0 + (seg & 7) * 8;
            const uint32_t doff = (uint32_t)r * 128 + ((uint32_t)ksb ^ (((uint32_t)r & 7) << 4));
            CP_ASYNC16(dbase + doff, A + (size_t)(m0 + r) * lda + kelt);
        }
#pragma unroll
        for (int it = 0; it < NT / 32; ++it) {
            const int seg = it * 256 + tid;
            const int r = seg >> 3;
            const int ksb = (seg & 7) * 16;
            const int kelt = k0 + (seg & 7) * 8;
            const uint32_t doff = (uint32_t)r * 128 + ((uint32_t)ksb ^ (((uint32_t)r & 7) << 4));
            CP_ASYNC16(dbase + 16384 + doff, Wt + (size_t)r * Kpad + kelt);
        }
        CP_COMMIT();
    };

    auto compute = [&](int buf) {
        const uint32_t ab = sb + buf * STAGE;
        const uint32_t bb = ab + 16384;
        const uint32_t xm = ((uint32_t)lane & 7) << 4;
        const int ra = ((lane >> 3) & 1) * 8 + (lane & 7);
        const int ka = ((lane >> 4) & 1) * 16;
        const int rb = ((lane >> 4) & 1) * 8 + (lane & 7);
        const int kb = ((lane >> 3) & 1) * 16;
#pragma unroll
        for (int s = 0; s < 4; ++s) {
            const int ksb = s * 32;
            uint32_t Ah[MT][4], Bh[4][2];
#pragma unroll
            for (int mt = 0; mt < MT; ++mt) {
                const uint32_t off = (uint32_t)(wm0 + mt * 16 + ra) * 128 +
                                     (((uint32_t)(ksb + ka)) ^ xm);
                LDSM4(Ah[mt][0], Ah[mt][1], Ah[mt][2], Ah[mt][3], ab + off);
            }
#pragma unroll
            for (int p = 0; p < 2; ++p) {
                const uint32_t off = (uint32_t)(wn0 + p * 16 + rb) * 128 +
                                     (((uint32_t)(ksb + kb)) ^ xm);
                LDSM4(Bh[2 * p][0], Bh[2 * p][1], Bh[2 * p + 1][0], Bh[2 * p + 1][1], bb + off);
            }
#pragma unroll
            for (int mt = 0; mt < MT; ++mt)
#pragma unroll
                for (int nt = 0; nt < 4; ++nt)
                    MMA16816(acc[mt][nt], Ah[mt], Bh[nt][0], Bh[nt][1]);
        }
    };

    issue(0, 0);
    issue(1, 1);
    for (int c = 0; c < NC; ++c) {
        cp_wait<1>();
        __syncthreads();
        compute(c % 3);
        if (c + 2 < NC) issue(c + 2, (c + 2) % 3);
        else CP_COMMIT();
    }

    const int g = lane >> 2, t = lane & 3;
#pragma unroll
    for (int mt = 0; mt < MT; ++mt) {
#pragma unroll
        for (int nt = 0; nt < 4; ++nt) {
            const int col = wn0 + nt * 8 + t * 2;
            float v0 = acc[mt][nt][0], v1 = acc[mt][nt][1];
            float v2 = acc[mt][nt][2], v3 = acc[mt][nt][3];
            const int row0 = m0 + wm0 + mt * 16 + g;
            if (EPI >= 1) {
                const float bv0 = bias[col], bv1 = bias[col + 1];
                v0 += bv0; v1 += bv1; v2 += bv0; v3 += bv1;
                if (ACT == 1) { v0 = fmaxf(v0, 0.f); v1 = fmaxf(v1, 0.f); v2 = fmaxf(v2, 0.f); v3 = fmaxf(v3, 0.f); }
                if (ACT == 2) { v0 = tanhf(v0); v1 = tanhf(v1); v2 = tanhf(v2); v3 = tanhf(v3); }
                const size_t o0 = (size_t)zb * c_off + (size_t)row0 * ldc + n0g + col;
                const size_t o1 = (size_t)zb * c_off + (size_t)(row0 + 8) * ldc + n0g + col;
                *(uint32_t*)(Ch + o0) = packh2(v0, v1);
                *(uint32_t*)(Ch + o1) = packh2(v2, v3);
                if (EPI == 2) {
                    long long ti0, ti1;
                    if (d_is64) {
                        ti0 = ((const long long*)tidx)[row0];
                        ti1 = ((const long long*)tidx)[row0 + 8];
                    } else {
                        ti0 = (long long)((const int*)tidx)[row0];
                        ti1 = (long long)((const int*)tidx)[row0 + 8];
                    }
                    const int gc = n0g + col;
                    float2 e0 = *(const float2*)(emb + (size_t)ti0 * Hn + gc);
                    float2 e1 = *(const float2*)(emb + (size_t)ti1 * Hn + gc);
                    float r0 = fmaxf(v0 * e0.x, 0.f);
                    float r1 = fmaxf(v1 * e0.y, 0.f);
                    float r2 = fmaxf(v2 * e1.x, 0.f);
                    float r3 = fmaxf(v3 * e1.y, 0.f);
                    *(uint32_t*)(relp + o0) = packh2(r0, r1);
                    *(uint32_t*)(relp + o1) = packh2(r2, r3);
                }
            } else {
                const int rem = N_STORE - n0g;
                const float bv0 = (col < rem) ? bias[col] : 0.f;
                const float bv1 = (col + 1 < rem) ? bias[col + 1] : 0.f;
                v0 += bv0; v1 += bv1; v2 += bv0; v3 += bv1;
                if (ACT == 1) { v0 = fmaxf(v0, 0.f); v1 = fmaxf(v1, 0.f); v2 = fmaxf(v2, 0.f); v3 = fmaxf(v3, 0.f); }
                if (ACT == 2) { v0 = tanhf(v0); v1 = tanhf(v1); v2 = tanhf(v2); v3 = tanhf(v3); }
                float* Cb = C + (size_t)zb * c_off + n0g;
                if (col < rem) {
                    Cb[(size_t)row0 * ldc + col] = v0;
                    Cb[(size_t)(row0 + 8) * ldc + col] = v2;
                }
                if (col + 1 < rem) {
                    Cb[(size_t)row0 * ldc + col + 1] = v1;
                    Cb[(size_t)(row0 + 8) * ldc + col + 1] = v3;
                }
            }
        }
    }
}

// ===================== routing GEMM, both nets one launch (z=6) =====================
__global__ __launch_bounds__(256, 2) void routegemm(
    const __half* __restrict__ A,
    const __half* __restrict__ WtA, const __half* __restrict__ WtC,
    const float* __restrict__ rbA, const float* __restrict__ rbC,
    float* __restrict__ pA, float* __restrict__ pC)
{
    extern __shared__ char smem[];
    const uint32_t sb = smem_to_u32(smem);
    const int tid = threadIdx.x, wid = tid >> 5, lane = tid & 31;
    const int m0 = blockIdx.x * 128;
    const int zb = blockIdx.z;
    const int net = zb / 3, l = zb % 3;
    const __half* Wt = (net ? WtC : WtA) + (size_t)l * 64 * 512;
    const float* bias = (net ? rbC : rbA) + l * 64;
    float* C = (net ? pC : pA) + (size_t)l * 64;

    constexpr int STAGE = 16384 + 8192;
    const int wm0 = (wid % 4) * 32;
    const int wn0 = (wid / 4) * 32;

    float acc[2][4][4];
#pragma unroll
    for (int mt = 0; mt < 2; ++mt)
#pragma unroll
        for (int nt = 0; nt < 4; ++nt)
#pragma unroll
            for (int e = 0; e < 4; ++e) acc[mt][nt][e] = 0.f;

    auto issue = [&](int c, int buf) {
        const int k0 = c << 6;
        const uint32_t dbase = sb + buf * STAGE;
#pragma unroll
        for (int it = 0; it < 4; ++it) {
            const int seg = it * 256 + tid;
            const int r = seg >> 3;
            const int ks = (seg & 7) * 16;
            const uint32_t doff = (uint32_t)r * 128 + ((uint32_t)ks ^ (((uint32_t)r & 7) << 4));
            CP_ASYNC16(dbase + doff, A + (size_t)(m0 + r) * Hn + k0 + (seg & 7) * 8);
        }
        {
#pragma unroll
            for (int it = 0; it < 2; ++it) {
                const int s2 = it * 256 + tid;
                const int r = s2 >> 3;
                const int ks = (s2 & 7) * 16;
                const uint32_t doff = (uint32_t)r * 128 + ((uint32_t)ks ^ (((uint32_t)r & 7) << 4));
                CP_ASYNC16(dbase + 16384 + doff, Wt + (size_t)r * 512 + k0 + (s2 & 7) * 8);
            }
        }
        CP_COMMIT();
    };

    auto compute = [&](int buf) {
        const uint32_t ab = sb + buf * STAGE;
        const uint32_t bb = ab + 16384;
        const uint32_t xm = ((uint32_t)lane & 7) << 4;
        const int ra = ((lane >> 3) & 1) * 8 + (lane & 7);
        const int ka = ((lane >> 4) & 1) * 16;
        const int rb = ((lane >> 4) & 1) * 8 + (lane & 7);
        const int kb = ((lane >> 3) & 1) * 16;
#pragma unroll
        for (int s = 0; s < 4; ++s) {
            const int ksb = s * 32;
            uint32_t Ah[2][4], Bh[4][2];
#pragma unroll
            for (int mt = 0; mt < 2; ++mt) {
                const uint32_t off = (uint32_t)(wm0 + mt * 16 + ra) * 128 +
                                     (((uint32_t)(ksb + ka)) ^ xm);
                LDSM4(Ah[mt][0], Ah[mt][1], Ah[mt][2], Ah[mt][3], ab + off);
            }
#pragma unroll
            for (int p = 0; p < 2; ++p) {
                const uint32_t off = (uint32_t)(wn0 + p * 16 + rb) * 128 +
                                     (((uint32_t)(ksb + kb)) ^ xm);
                LDSM4(Bh[2 * p][0], Bh[2 * p][1], Bh[2 * p + 1][0], Bh[2 * p + 1][1], bb + off);
            }
#pragma unroll
            for (int mt = 0; mt < 2; ++mt)
#pragma unroll
                for (int nt = 0; nt < 4; ++nt)
                    MMA16816(acc[mt][nt], Ah[mt], Bh[nt][0], Bh[nt][1]);
        }
    };

    issue(0, 0);
    issue(1, 1);
    for (int c = 0; c < 8; ++c) {
        cp_wait<1>();
        __syncthreads();
        compute(c % 3);
        if (c + 2 < 8) issue(c + 2, (c + 2) % 3);
        else CP_COMMIT();
    }

    const int g = lane >> 2, t = lane & 3;
#pragma unroll
    for (int mt = 0; mt < 2; ++mt) {
#pragma unroll
        for (int nt = 0; nt < 4; ++nt) {
            const int col = wn0 + nt * 8 + t * 2;
            if (col < 64) {
                const float bv0 = bias[col], bv1 = bias[col + 1];
                const int row0 = m0 + wm0 + mt * 16 + g;
                C[(size_t)row0 * (L1n * 64) + col]     = acc[mt][nt][0] + bv0;
                C[(size_t)row0 * (L1n * 64) + col + 1] = acc[mt][nt][1] + bv1;
                C[(size_t)(row0 + 8) * (L1n * 64) + col]     = acc[mt][nt][2] + bv0;
                C[(size_t)(row0 + 8) * (L1n * 64) + col + 1] = acc[mt][nt][3] + bv1;
            }
        }
    }
}

// ===================== module GEMM: 128x128, 256 thr, z=16 =====================
__global__ __launch_bounds__(256, 2) void modgemm2(
    const __half* __restrict__ Ac, const __half* __restrict__ Aa, int lda, int amod,
    const __half* __restrict__ Wc, const __half* __restrict__ Wa,
    const float* __restrict__ biasC, const float* __restrict__ biasA,
    __half* __restrict__ outC, __half* __restrict__ outA)
{
    extern __shared__ char smem[];
    const uint32_t sb = smem_to_u32(smem);
    const int tid = threadIdx.x, wid = tid >> 5, lane = tid & 31;
    const int m0 = blockIdx.x * 128;
    const int n0g = blockIdx.y * 128;
    const int zb = blockIdx.z;
    const int net = zb >> 3, m = zb & 7;
    const __half* A  = (net ? Aa : Ac) + (size_t)m * amod;
    const __half* Wt = (net ? Wa : Wc) + (size_t)m * 512 * 512 + (size_t)n0g * 512;
    const float* bias = (net ? biasA : biasC) + m * 512 + n0g;
    __half* Ch = net ? outA : outC;

    constexpr int STAGE = 32768;
    const int wm0 = (wid & 1) * 64;
    const int wn0 = (wid >> 1) * 32;

    float acc[4][4][4];
#pragma unroll
    for (int mt = 0; mt < 4; ++mt)
#pragma unroll
        for (int nt = 0; nt < 4; ++nt)
#pragma unroll
            for (int e = 0; e < 4; ++e) acc[mt][nt][e] = 0.f;

    auto issue = [&](int c, int buf) {
        const int k0 = c << 6;
        const uint32_t dbase = sb + buf * STAGE;
#pragma unroll
        for (int it = 0; it < 4; ++it) {
            const int seg = it * 256 + tid;
            const int r = seg >> 3;
            const int ks = (seg & 7) * 16;
            const uint32_t doff = (uint32_t)r * 128 + ((uint32_t)ks ^ (((uint32_t)r & 7) << 4));
            CP_ASYNC16(dbase + doff, A + (size_t)(m0 + r) * lda + k0 + (seg & 7) * 8);
        }
#pragma unroll
        for (int it = 0; it < 4; ++it) {
            const int seg = it * 256 + tid;
            const int r = seg >> 3;
            const int ks = (seg & 7) * 16;
            const uint32_t doff = (uint32_t)r * 128 + ((uint32_t)ks ^ (((uint32_t)r & 7) << 4));
            CP_ASYNC16(dbase + 16384 + doff, Wt + (size_t)r * 512 + k0 + (seg & 7) * 8);
        }
        CP_COMMIT();
    };

    auto compute = [&](int buf) {
        const uint32_t ab = sb + buf * STAGE;
        const uint32_t bb = ab + 16384;
        const uint32_t xm = ((uint32_t)lane & 7) << 4;
        const int ra = ((lane >> 3) & 1) * 8 + (lane & 7);
        const int ka = ((lane >> 4) & 1) * 16;
        const int rb = ((lane >> 4) & 1) * 8 + (lane & 7);
        const int kb = ((lane >> 3) & 1) * 16;
#pragma unroll
        for (int s = 0; s < 4; ++s) {
            const int ksb = s * 32;
            uint32_t Ah[4][4], Bh[4][2];
#pragma unroll
            for (int mt = 0; mt < 4; ++mt) {
                const uint32_t off = (uint32_t)(wm0 + mt * 16 + ra) * 128 +
                                     (((uint32_t)(ksb + ka)) ^ xm);
                LDSM4(Ah[mt][0], Ah[mt][1], Ah[mt][2], Ah[mt][3], ab + off);
            }
#pragma unroll
            for (int p = 0; p < 2; ++p) {
                const uint32_t off = (uint32_t)(wn0 + p * 16 + rb) * 128 +
                                     (((uint32_t)(ksb + kb)) ^ xm);
                LDSM4(Bh[2 * p][0], Bh[2 * p][1], Bh[2 * p + 1][0], Bh[2 * p + 1][1], bb + off);
            }
#pragma unroll
            for (int mt = 0; mt < 4; ++mt)
#pragma unroll
                for (int nt = 0; nt < 4; ++nt)
                    MMA16816(acc[mt][nt], Ah[mt], Bh[nt][0], Bh[nt][1]);
        }
    };

    issue(0, 0);
    issue(1, 1);
    for (int c = 0; c < 8; ++c) {
        cp_wait<1>();
        __syncthreads();
        compute(c % 3);
        if (c + 2 < 8) issue(c + 2, (c + 2) % 3);
        else CP_COMMIT();
    }

    const int g = lane >> 2, t = lane & 3;
#pragma unroll
    for (int mt = 0; mt < 4; ++mt) {
#pragma unroll
        for (int nt = 0; nt < 4; ++nt) {
            const int col = wn0 + nt * 8 + t * 2;
            const float bv0 = bias[col], bv1 = bias[col + 1];
            float v0 = fmaxf(acc[mt][nt][0] + bv0, 0.f);
            float v1 = fmaxf(acc[mt][nt][1] + bv1, 0.f);
            float v2 = fmaxf(acc[mt][nt][2] + bv0, 0.f);
            float v3 = fmaxf(acc[mt][nt][3] + bv1, 0.f);
            const int row0 = m0 + wm0 + mt * 16 + g;
            const size_t o0 = (size_t)row0 * 4096 + m * 512 + n0g + col;
            const size_t o1 = (size_t)(row0 + 8) * 4096 + m * 512 + n0g + col;
            *(uint32_t*)(Ch + o0) = packh2(v0, v1);
            *(uint32_t*)(Ch + o1) = packh2(v2, v3);
        }
    }
}

// ===================== softmax over groups of 8 =====================
__global__ void softmax_kernel(float* __restrict__ pA, float* __restrict__ pC) {
    const int gid = blockIdx.x * blockDim.x + threadIdx.x;
    const int per = Bn * L1n * 8;
    float* p = (gid < per) ? (pA + (size_t)gid * 8) : (pC + (size_t)(gid - per) * 8);
    float v[8], mx = -1e30f;
#pragma unroll
    for (int j = 0; j < 8; j++) { v[j] = p[j]; mx = fmaxf(mx, v[j]); }
    float s = 0.f;
#pragma unroll
    for (int j = 0; j < 8; j++) { v[j] = __expf(v[j] - mx); s += v[j]; }
    const float inv = 1.f / s;
#pragma unroll
    for (int j = 0; j < 8; j++) p[j] = v[j] * inv;
}

// ===================== fused mix, 2 samples per block =====================
__global__ void mix2_kernel(const float* __restrict__ pC, const float* __restrict__ pA,
                            const __half* __restrict__ opc, const __half* __restrict__ opa,
                            __half* __restrict__ gc, __half* __restrict__ ga) {
    __shared__ float p[2][64];
    const int net = blockIdx.y, tid = threadIdx.x;
    const int sub = tid >> 7, t = tid & 127;
    const int b = blockIdx.x * 2 + sub;
    const float* probs = net ? pA : pC;
    const __half* op = net ? opa : opc;
    __half* gp = net ? ga : gc;
    if (t < 64) p[sub][t] = probs[(size_t)b * (L1n * 64) + t];
    __syncthreads();
    const size_t base = (size_t)b * 4096 + t * 4;
    float o[8][4];
#pragma unroll
    for (int j = 0; j < 8; j++) {
        uint2 u = *(const uint2*)(op + base + j * 512);
        float2 a = h2f2(u.x), c = h2f2(u.y);
        o[j][0] = a.x; o[j][1] = a.y; o[j][2] = c.x; o[j][3] = c.y;
    }
#pragma unroll
    for (int i = 0; i < 8; i++) {
        float a0 = 0.f, a1 = 0.f, a2 = 0.f, a3 = 0.f;
#pragma unroll
        for (int j = 0; j < 8; j++) {
            const float w = p[sub][i * 8 + j];
            a0 = fmaf(w, o[j][0], a0);
            a1 = fmaf(w, o[j][1], a1);
            a2 = fmaf(w, o[j][2], a2);
            a3 = fmaf(w, o[j][3], a3);
        }
        uint2 u;
        u.x = packh2(a0, a1);
        u.y = packh2(a2, a3);
        *(uint2*)(gp + base + i * 512) = u;
    }
}

// ===================== critic + pack fused =====================
__global__ void critpack_kernel(const __half* __restrict__ gp, const float* __restrict__ wf,
                                const float* __restrict__ actorOut, float* __restrict__ out) {
    const int w = (blockIdx.x * blockDim.x + threadIdx.x) >> 5;
    const int lane = threadIdx.x & 31;
    const size_t off = (size_t)w * (Mn * Hn);
    float s = 0.f;
    for (int i = lane * 2; i < Mn * Hn; i += 64) {
        float2 g = h2f2(*(const uint32_t*)(gp + off + i));
        float2 f = *(const float2*)(wf + i);
        s = fmaf(g.x, f.x, s);
        s = fmaf(g.y, f.y, s);
    }
#pragma unroll
    for (int o = 16; o > 0; o >>= 1) s += __shfl_xor_sync(0xFFFFFFFFu, s, o);
    if (lane < An)       out[(size_t)w * 20 + lane] = actorOut[(size_t)w * An + lane];
    else if (lane == 17) out[(size_t)w * 20 + 17] = d_cst[17];
    else if (lane == 18) out[(size_t)w * 20 + 18] = d_cst[18];
    else if (lane == 19) out[(size_t)w * 20 + 19] = s + d_cst[19];
}

// ===================== host =====================
extern "C" void kernel_launch(void* const* d_in, const int* in_sizes, int n_in,
                              void* d_out, int out_size) {
    const float* x      = (const float*)d_in[0];
    const void*  tidx   = d_in[1];
    const float* W1     = (const float*)d_in[2];
    const float* b1     = (const float*)d_in[3];
    const float* W2     = (const float*)d_in[4];
    const float* b2     = (const float*)d_in[5];
    const float* emb    = (const float*)d_in[6];
    const float* a_rW   = (const float*)d_in[7];
    const float* a_rb   = (const float*)d_in[8];
    const float* c_rW   = (const float*)d_in[9];
    const float* c_rb   = (const float*)d_in[10];
    const float* a_W    = (const float*)d_in[11];
    const float* a_b    = (const float*)d_in[12];
    const float* a_Wf   = (const float*)d_in[13];
    const float* a_bf   = (const float*)d_in[14];
    const float* c_W    = (const float*)d_in[15];
    const float* c_b    = (const float*)d_in[16];
    const float* c_Wf   = (const float*)d_in[17];
    const float* c_bf   = (const float*)d_in[18];
    const float* logstd = (const float*)d_in[19];
    float* out = (float*)d_out;

    float *pA, *pC, *actorOut, *cst;
    __half *xp, *h1p, *fsp, *rp, *opc, *opa, *gc0, *gc1, *gc2, *ga0, *ga1;
    __half *we1, *we2, *war, *wcr, *wa, *wc, *waf;
    cudaGetSymbolAddress((void**)&pA, d_probsA);
    cudaGetSymbolAddress((void**)&pC, d_probsC);
    cudaGetSymbolAddress((void**)&actorOut, d_actorOut);
    cudaGetSymbolAddress((void**)&cst, d_cst);
    cudaGetSymbolAddress((void**)&xp, p_x);
    cudaGetSymbolAddress((void**)&h1p, p_h1);
    cudaGetSymbolAddress((void**)&fsp, p_fs);
    cudaGetSymbolAddress((void**)&rp, p_rel);
    cudaGetSymbolAddress((void**)&opc, p_outc);
    cudaGetSymbolAddress((void**)&opa, p_outa);
    cudaGetSymbolAddress((void**)&gc0, p_gc0);
    cudaGetSymbolAddress((void**)&gc1, p_gc1);
    cudaGetSymbolAddress((void**)&gc2, p_gc2);
    cudaGetSymbolAddress((void**)&ga0, p_ga0);
    cudaGetSymbolAddress((void**)&ga1, p_ga1);
    cudaGetSymbolAddress((void**)&we1, wt_e1);
    cudaGetSymbolAddress((void**)&we2, wt_e2);
    cudaGetSymbolAddress((void**)&war, wt_ar);
    cudaGetSymbolAddress((void**)&wcr, wt_cr);
    cudaGetSymbolAddress((void**)&wa, wt_a);
    cudaGetSymbolAddress((void**)&wc, wt_c);
    cudaGetSymbolAddress((void**)&waf, wt_af);

    const int SM128 = 3 * (16384 + 128 * 128);   // 98304
    const int SM64  = 3 * (16384 + 64 * 128);    // 73728
    const int SMRT  = 3 * (16384 + 8192);        // 73728
    cudaFuncSetAttribute(mmagemm<128, 2, 2, 1>, cudaFuncAttributeMaxDynamicSharedMemorySize, SM128);
    cudaFuncSetAttribute(mmagemm<128, 2, 2, 2>, cudaFuncAttributeMaxDynamicSharedMemorySize, SM128);
    cudaFuncSetAttribute(mmagemm<64, 4, 0, 0>,  cudaFuncAttributeMaxDynamicSharedMemorySize, SM64);
    cudaFuncSetAttribute(routegemm, cudaFuncAttributeMaxDynamicSharedMemorySize, SMRT);
    cudaFuncSetAttribute(modgemm2, cudaFuncAttributeMaxDynamicSharedMemorySize, SM128);

    // prolog: splitx + detect + prep
    prolog_kernel<<<(Bn * 96) / 256 + 2, 256>>>(x, xp, (const int*)tidx, a_bf, c_bf, logstd);

    // all weight conversions in one launch
    tconv_all<<<13184, 256>>>(W1, W2, a_rW, c_rW, a_W, c_W, a_Wf,
                              we1, we2, war, wcr, wa, wc, waf);

    // encoder (GEMM2 fuses rel computation)
    mmagemm<128, 2, 2, 1><<<dim3(128, 4, 1), 256, SM128>>>(
        xp, 384, 0, we1, 384, 0, b1, 0,
        nullptr, h1p, Hn, 0, Hn, 6, nullptr, nullptr, nullptr);
    mmagemm<128, 2, 2, 2><<<dim3(128, 4, 1), 256, SM128>>>(
        h1p, Hn, 0, we2, 512, 0, b2, 0,
        nullptr, fsp, Hn, 0, Hn, 8, tidx, emb, rp);

    // routing, both nets in one launch
    routegemm<<<dim3(128, 1, 6), 256, SMRT>>>(rp, war, wcr, a_rb, c_rb, pA, pC);
    softmax_kernel<<<(2 * Bn * L1n * 8) / 256, 256>>>(pA, pC);

    // fused module layers
    {
        const __half* gcp = fsp;
        const __half* gap = fsp;
        __half* gcd[3] = {gc0, gc1, gc2};
        __half* gad[3] = {ga0, ga1, ga0};
        for (int l = 0; l < L1n; l++) {
            modgemm2<<<dim3(Bn / 128, 4, 16), 256, SM128>>>(
                gcp, gap,
                (l == 0) ? Hn : (Mn * Hn), (l == 0) ? 0 : Hn,
                wc + (size_t)l * Mn * 512 * 512, wa + (size_t)l * Mn * 512 * 512,
                c_b + (size_t)l * Mn * Hn, a_b + (size_t)l * Mn * Hn,
                opc, opa);
            mix2_kernel<<<dim3(Bn / 2, 2), 256>>>(pC + (size_t)l * 64, pA + (size_t)l * 64,
                                                  opc, opa, gcd[l], gad[l]);
            gcp = gcd[l]; gap = gad[l];
        }
    }

    // actor final
    mmagemm<64, 4, 0, 0><<<dim3(128, 1, 1), 256, SM64>>>(
        ga0, Mn * Hn, 0, waf, 4096, 0, cst, 0,
        actorOut, nullptr, An, 0, An, 64, nullptr, nullptr, nullptr);
    // critic dot + output pack fused
    critpack_kernel<<<Bn / 8, 256>>>(gc2, c_Wf, actorOut, out);
}